// round 11
// baseline (speedup 1.0000x reference)
#include <cuda_runtime.h>
#include <cuda_fp16.h>
#include <cstdint>
#include <math.h>

#define B_SZ 16384
#define H_SZ 512
#define G4   2048
#define OUTF 256
#define KPAD 288
#define IN0  257
#define MB   128          // row-blocks along batch = B/128

// ---------------- scratch (static device memory) ------------------------------
__device__ float g_inpPad[(size_t)B_SZ * KPAD];   // zero-padded concat(x,y)
__device__ float g_WxPad [(size_t)G4 * KPAD];     // zero-padded Wx0
__device__ float g_Zx    [(size_t)B_SZ * G4];
__device__ float g_Zh    [(size_t)B_SZ * G4];
__device__ float g_partX [(size_t)MB * G4 * 2];   // per-rowblock col (sum, sumsq)
__device__ float g_partH [(size_t)MB * G4 * 2];
__device__ float g_scX[G4], g_shX[G4], g_scH[G4], g_shH[G4];

// ---------------- helpers ------------------------------------------------------
__device__ __forceinline__ float sigm(float x) { return 1.f / (1.f + expf(-x)); }
__device__ __forceinline__ uint32_t packh2(float lo, float hi) {
    // half2 word: low 16 = lo, high 16 = hi (RN conversion), single F2FP.PACK
    uint32_t r;
    asm("cvt.rn.f16x2.f32 %0, %1, %2;" : "=r"(r) : "f"(hi), "f"(lo));
    return r;
}

// ---------------- prep kernels (padding only, fp32 passthrough) ----------------
__global__ void prep_inp(const float* __restrict__ x, const float* __restrict__ y,
                         float* __restrict__ o) {
    int idx = blockIdx.x * blockDim.x + threadIdx.x;   // B*KPAD
    int b = idx / KPAD, k = idx - b * KPAD;
    float v = (k < 256) ? x[(size_t)b * 256 + k] : (k == 256 ? y[b] : 0.f);
    o[idx] = v;
}
__global__ void prep_wx(const float* __restrict__ Wx, float* __restrict__ o) {
    int idx = blockIdx.x * blockDim.x + threadIdx.x;   // G4*KPAD
    int r = idx / KPAD, k = idx - r * KPAD;
    o[idx] = (k < IN0) ? Wx[(size_t)r * IN0 + k] : 0.f;
}

// ---------------- fp16 tensor-core GEMM: C[M,N] = A[M,K] * W[N,K]^T (+bias) ----
// block tile 128x128, BK=32 (=16 half2 words), 8 warps (4x2), warp tile 32x64,
// mma m16n8k16 f16 with f32 accumulate. Fused BN-statistics epilogue.
// smem rows: 16 half2 words + 4 pad (stride 20) -> fragment banks 20g+tg all
// distinct mod 32 => conflict-free LDS for both A and B fragments.
constexpr int BM = 128, BN = 128, BK = 32;
constexpr int SW = 20;                 // words per smem row (16 + 4 pad)

__global__ __launch_bounds__(256, 2) void gemm_tn(
    float* __restrict__ C, const float* __restrict__ A, int lda,
    const float* __restrict__ W, int ldw, int M, int N, int K,
    const float* __restrict__ bias, float* __restrict__ part)
{
    __shared__ __align__(16) uint32_t As[BM][SW];
    __shared__ __align__(16) uint32_t Ws[BN][SW];
    const int tid  = threadIdx.x;
    const int lane = tid & 31, warp = tid >> 5;
    const int g    = lane >> 2, tg = lane & 3;       // groupID, threadID_in_group
    const int wm   = warp >> 1, wn = warp & 1;
    const int mW   = wm * 32, nW = wn * 64;
    const int bM   = blockIdx.y * BM, bN = blockIdx.x * BN;

    float acc[2][8][4];
#pragma unroll
    for (int i = 0; i < 2; i++)
#pragma unroll
        for (int j = 0; j < 8; j++)
#pragma unroll
            for (int r = 0; r < 4; r++) acc[i][j][r] = 0.f;

    for (int k0 = 0; k0 < K; k0 += BK) {
        float4 av[4], wv[4];
#pragma unroll
        for (int i = 0; i < 4; i++) {
            int idx = tid + i * 256;
            int r = idx >> 3, c4 = idx & 7;          // 8 float4 per 32-float row
            av[i] = *(const float4*)(A + (size_t)(bM + r) * lda + (k0 + c4 * 4));
            wv[i] = *(const float4*)(W + (size_t)(bN + r) * ldw + (k0 + c4 * 4));
        }
        __syncthreads();   // previous iteration's compute done before overwrite
#pragma unroll
        for (int i = 0; i < 4; i++) {
            int idx = tid + i * 256;
            int r = idx >> 3, w0 = (idx & 7) * 2;    // word pair w0, w0+1
            *(uint2*)&As[r][w0] = make_uint2(packh2(av[i].x, av[i].y),
                                             packh2(av[i].z, av[i].w));
            *(uint2*)&Ws[r][w0] = make_uint2(packh2(wv[i].x, wv[i].y),
                                             packh2(wv[i].z, wv[i].w));
        }
        __syncthreads();
        // 2 k-steps of 16: words ks*8 + {tg, tg+4}
#pragma unroll
        for (int ks = 0; ks < 2; ks++) {
            const int wb = ks * 8;
            uint32_t a[2][4], b[8][2];
#pragma unroll
            for (int mt = 0; mt < 2; mt++) {
                int r0 = mW + mt * 16 + g;
                a[mt][0] = As[r0    ][wb + tg];
                a[mt][1] = As[r0 + 8][wb + tg];
                a[mt][2] = As[r0    ][wb + tg + 4];
                a[mt][3] = As[r0 + 8][wb + tg + 4];
            }
#pragma unroll
            for (int nt = 0; nt < 8; nt++) {
                int rn = nW + nt * 8 + g;
                b[nt][0] = Ws[rn][wb + tg];
                b[nt][1] = Ws[rn][wb + tg + 4];
            }
#pragma unroll
            for (int mt = 0; mt < 2; mt++)
#pragma unroll
                for (int nt = 0; nt < 8; nt++)
                    asm volatile(
                        "mma.sync.aligned.m16n8k16.row.col.f32.f16.f16.f32 "
                        "{%0,%1,%2,%3},{%4,%5,%6,%7},{%8,%9},{%0,%1,%2,%3};\n"
                        : "+f"(acc[mt][nt][0]), "+f"(acc[mt][nt][1]),
                          "+f"(acc[mt][nt][2]), "+f"(acc[mt][nt][3])
                        : "r"(a[mt][0]), "r"(a[mt][1]), "r"(a[mt][2]), "r"(a[mt][3]),
                          "r"(b[nt][0]), "r"(b[nt][1]));
        }
    }

    // ---- C-tile writeback (registers only; no smem dependency) ----
#pragma unroll
    for (int mt = 0; mt < 2; mt++) {
        int r0 = bM + mW + mt * 16 + g;
#pragma unroll
        for (int nt = 0; nt < 8; nt++) {
            int c = bN + nW + nt * 8 + 2 * tg;
            float b0 = 0.f, b1 = 0.f;
            if (bias) { b0 = bias[c]; b1 = bias[c + 1]; }
            *(float2*)(C + (size_t)r0 * N + c)       = make_float2(acc[mt][nt][0] + b0, acc[mt][nt][1] + b1);
            *(float2*)(C + (size_t)(r0 + 8) * N + c) = make_float2(acc[mt][nt][2] + b0, acc[mt][nt][3] + b1);
        }
    }

    // ---- fused BN statistics: per-block column (sum, sumsq) partials ----
    if (part) {
        __syncthreads();                       // all warps done reading As/Ws
        float* psm = (float*)&As[0][0];        // reuse smem: [4 wm][128 col][2]
#pragma unroll
        for (int nt = 0; nt < 8; nt++) {
            float s0 = 0.f, q0 = 0.f, s1 = 0.f, q1 = 0.f;
#pragma unroll
            for (int mt = 0; mt < 2; mt++) {
                float v0 = acc[mt][nt][0], v2 = acc[mt][nt][2];
                float v1 = acc[mt][nt][1], v3 = acc[mt][nt][3];
                s0 += v0 + v2; q0 += v0 * v0 + v2 * v2;
                s1 += v1 + v3; q1 += v1 * v1 + v3 * v3;
            }
            // reduce over g (8 lanes: stride 16, 8, 4 in lane space)
#pragma unroll
            for (int off = 16; off >= 4; off >>= 1) {
                s0 += __shfl_xor_sync(0xFFFFFFFFu, s0, off);
                q0 += __shfl_xor_sync(0xFFFFFFFFu, q0, off);
                s1 += __shfl_xor_sync(0xFFFFFFFFu, s1, off);
                q1 += __shfl_xor_sync(0xFFFFFFFFu, q1, off);
            }
            if (g == 0) {
                int col = nW + nt * 8 + 2 * tg;       // 0..127 within block
                psm[(wm * 128 + col) * 2 + 0]     = s0;
                psm[(wm * 128 + col) * 2 + 1]     = q0;
                psm[(wm * 128 + col + 1) * 2 + 0] = s1;
                psm[(wm * 128 + col + 1) * 2 + 1] = q1;
            }
        }
        __syncthreads();
        {   // 256 threads: fold 4 wm quarters -> 128 cols x {s,q}
            int col = tid >> 1, sq = tid & 1;
            float v = psm[(col) * 2 + sq] + psm[(128 + col) * 2 + sq]
                    + psm[(256 + col) * 2 + sq] + psm[(384 + col) * 2 + sq];
            part[((size_t)blockIdx.y * N + bN + col) * 2 + sq] = v;
        }
    }
}

// ---------------- fold partials into BN affine scale/shift ---------------------
__global__ void stats_final(const float* __restrict__ gx, const float* __restrict__ bx,
                            const float* __restrict__ gh, const float* __restrict__ bh) {
    int j = blockIdx.x * blockDim.x + threadIdx.x;     // 2048
    float sx = 0.f, qx = 0.f, sh = 0.f, qh = 0.f;
    for (int rb = 0; rb < MB; rb++) {
        size_t o = ((size_t)rb * G4 + j) * 2;
        sx += g_partX[o]; qx += g_partX[o + 1];
        sh += g_partH[o]; qh += g_partH[o + 1];
    }
    const float invB = 1.f / (float)B_SZ;
    float mx = sx * invB, vx = qx * invB - mx * mx;
    float ax = gx[j] * rsqrtf(vx + 1e-5f);
    g_scX[j] = ax; g_shX[j] = bx[j] - mx * ax;
    float mh = sh * invB, vh = qh * invB - mh * mh;
    float ah = gh[j] * rsqrtf(vh + 1e-5f);
    g_scH[j] = ah; g_shH[j] = bh[j] - mh * ah;
}

// ---------------- fused BN + LSTM cell (float4 vectorized) ---------------------
__global__ void cell_kernel(const float* __restrict__ Zx, const float* __restrict__ Zh,
                            const float* __restrict__ cPrev,
                            float* __restrict__ hOut, float* __restrict__ cOut) {
    int t = blockIdx.x * blockDim.x + threadIdx.x;     // B*128 threads
    int jv = t & 127, b = t >> 7;                      // jv: float4 index in 512
    size_t base4 = ((size_t)b << 9) + jv;              // float4 units of 2048-row
    const float4* zx = (const float4*)Zx;
    const float4* zh = (const float4*)Zh;
    float4 zf4 = zx[base4      ], hf4 = zh[base4      ];
    float4 zi4 = zx[base4 + 128], hi4 = zh[base4 + 128];
    float4 zo4 = zx[base4 + 256], ho4 = zh[base4 + 256];
    float4 zg4 = zx[base4 + 384], hg4 = zh[base4 + 384];
    const float4* scX = (const float4*)g_scX; const float4* shX = (const float4*)g_shX;
    const float4* scH = (const float4*)g_scH; const float4* shH = (const float4*)g_shH;
    float4 sxf = scX[jv], txf = shX[jv], shf = scH[jv], thf = shH[jv];
    float4 sxi = scX[jv + 128], txi = shX[jv + 128], shi = scH[jv + 128], thi = shH[jv + 128];
    float4 sxo = scX[jv + 256], txo = shX[jv + 256], sho = scH[jv + 256], tho = shH[jv + 256];
    float4 sxg = scX[jv + 384], txg = shX[jv + 384], shg = scH[jv + 384], thg = shH[jv + 384];
    float4 cp = ((const float4*)cPrev)[((size_t)b << 7) + jv];

    float zf[4] = { zf4.x*sxf.x+txf.x + hf4.x*shf.x+thf.x, zf4.y*sxf.y+txf.y + hf4.y*shf.y+thf.y,
                    zf4.z*sxf.z+txf.z + hf4.z*shf.z+thf.z, zf4.w*sxf.w+txf.w + hf4.w*shf.w+thf.w };
    float zi[4] = { zi4.x*sxi.x+txi.x + hi4.x*shi.x+thi.x, zi4.y*sxi.y+txi.y + hi4.y*shi.y+thi.y,
                    zi4.z*sxi.z+txi.z + hi4.z*shi.z+thi.z, zi4.w*sxi.w+txi.w + hi4.w*shi.w+thi.w };
    float zo[4] = { zo4.x*sxo.x+txo.x + ho4.x*sho.x+tho.x, zo4.y*sxo.y+txo.y + ho4.y*sho.y+tho.y,
                    zo4.z*sxo.z+txo.z + ho4.z*sho.z+tho.z, zo4.w*sxo.w+txo.w + ho4.w*sho.w+tho.w };
    float zg[4] = { zg4.x*sxg.x+txg.x + hg4.x*shg.x+thg.x, zg4.y*sxg.y+txg.y + hg4.y*shg.y+thg.y,
                    zg4.z*sxg.z+txg.z + hg4.z*shg.z+thg.z, zg4.w*sxg.w+txg.w + hg4.w*shg.w+thg.w };
    float cpv[4] = { cp.x, cp.y, cp.z, cp.w };
    float h[4], c[4];
#pragma unroll
    for (int i = 0; i < 4; i++) {
        c[i] = sigm(zf[i]) * cpv[i] + sigm(zi[i]) * tanhf(zg[i]);
        h[i] = sigm(zo[i]) * tanhf(c[i]);
    }
    ((float4*)hOut)[((size_t)b << 7) + jv] = make_float4(h[0], h[1], h[2], h[3]);
    ((float4*)cOut)[((size_t)b << 7) + jv] = make_float4(c[0], c[1], c[2], c[3]);
}

// ---------------- launch -------------------------------------------------------
extern "C" void kernel_launch(void* const* d_in, const int* in_sizes, int n_in,
                              void* d_out, int out_size) {
    const float* x   = (const float*)d_in[0];
    const float* y   = (const float*)d_in[1];
    const float* h0  = (const float*)d_in[2];
    const float* c0  = (const float*)d_in[3];
    const float* Wx0 = (const float*)d_in[4];
    const float* Wh0 = (const float*)d_in[5];
    const float* gx0 = (const float*)d_in[6];
    const float* bx0 = (const float*)d_in[7];
    const float* gh0 = (const float*)d_in[8];
    const float* bh0 = (const float*)d_in[9];
    const float* Wx1 = (const float*)d_in[10];
    const float* Wh1 = (const float*)d_in[11];
    const float* gx1 = (const float*)d_in[12];
    const float* bx1 = (const float*)d_in[13];
    const float* gh1 = (const float*)d_in[14];
    const float* bh1 = (const float*)d_in[15];
    const float* Wo  = (const float*)d_in[16];
    const float* bo  = (const float*)d_in[17];
    float* out = (float*)d_out;

    float *inp, *wxp, *Zx, *Zh, *partX, *partH;
    cudaGetSymbolAddress((void**)&inp,   g_inpPad);
    cudaGetSymbolAddress((void**)&wxp,   g_WxPad);
    cudaGetSymbolAddress((void**)&Zx,    g_Zx);
    cudaGetSymbolAddress((void**)&Zh,    g_Zh);
    cudaGetSymbolAddress((void**)&partX, g_partX);
    cudaGetSymbolAddress((void**)&partH, g_partH);

    // output layout: out[B,256], h1[B,512], h2[B,512], c1[B,512], c2[B,512]
    float* h1 = out + (size_t)B_SZ * OUTF;
    float* h2 = h1 + (size_t)B_SZ * H_SZ;
    float* c1 = h2 + (size_t)B_SZ * H_SZ;
    float* c2 = c1 + (size_t)B_SZ * H_SZ;
    const float* h00 = h0;
    const float* h01 = h0 + (size_t)B_SZ * H_SZ;
    const float* c00 = c0;
    const float* c01 = c0 + (size_t)B_SZ * H_SZ;

    const int BH = B_SZ * H_SZ;

    prep_inp<<<(B_SZ * KPAD) / 256, 256>>>(x, y, inp);
    prep_wx<<<(G4 * KPAD) / 256, 256>>>(Wx0, wxp);

    dim3 gg(G4 / BN, B_SZ / BM);     // 16 x 128
    dim3 go(OUTF / BN, B_SZ / BM);   // 2 x 128

    // layer 0
    gemm_tn<<<gg, 256>>>(Zx, inp, KPAD, wxp, KPAD, B_SZ, G4, KPAD, nullptr, partX);
    gemm_tn<<<gg, 256>>>(Zh, h00, H_SZ, Wh0, H_SZ, B_SZ, G4, H_SZ, nullptr, partH);
    stats_final<<<G4 / 256, 256>>>(gx0, bx0, gh0, bh0);
    cell_kernel<<<BH / 4 / 256, 256>>>(Zx, Zh, c00, h1, c1);

    // layer 1
    gemm_tn<<<gg, 256>>>(Zx, h1, H_SZ, Wx1, H_SZ, B_SZ, G4, H_SZ, nullptr, partX);
    gemm_tn<<<gg, 256>>>(Zh, h01, H_SZ, Wh1, H_SZ, B_SZ, G4, H_SZ, nullptr, partH);
    stats_final<<<G4 / 256, 256>>>(gx1, bx1, gh1, bh1);
    cell_kernel<<<BH / 4 / 256, 256>>>(Zx, Zh, c01, h2, c2);

    // output projection (no stats)
    gemm_tn<<<go, 256>>>(out, h2, H_SZ, Wo, H_SZ, B_SZ, OUTF, H_SZ, bo, nullptr);
}

// round 12
// speedup vs baseline: 1.7088x; 1.7088x over previous
#include <cuda_runtime.h>
#include <cuda_fp16.h>
#include <cstdint>
#include <math.h>

#define B_SZ 16384
#define H_SZ 512
#define G4   2048
#define OUTF 256
#define KPAD 288
#define IN0  257
#define MB   128          // row-blocks along batch = B/128

// ---------------- scratch (static device memory) ------------------------------
// half operands stored as uint4-packed arrays (8 halves per uint4)
__device__ __align__(16) uint4 g_inpH [(size_t)B_SZ * (KPAD / 8)];
__device__ __align__(16) uint4 g_WxH  [(size_t)G4 * (KPAD / 8)];
__device__ __align__(16) uint4 g_h00H [(size_t)B_SZ * (H_SZ / 8)];
__device__ __align__(16) uint4 g_h01H [(size_t)B_SZ * (H_SZ / 8)];
__device__ __align__(16) uint4 g_h1H  [(size_t)B_SZ * (H_SZ / 8)];
__device__ __align__(16) uint4 g_h2H  [(size_t)B_SZ * (H_SZ / 8)];
__device__ __align__(16) uint4 g_Wh0H [(size_t)G4 * (H_SZ / 8)];
__device__ __align__(16) uint4 g_Wx1H [(size_t)G4 * (H_SZ / 8)];
__device__ __align__(16) uint4 g_Wh1H [(size_t)G4 * (H_SZ / 8)];
__device__ __align__(16) uint4 g_WoH  [(size_t)OUTF * (H_SZ / 8)];
__device__ float g_Zx   [(size_t)B_SZ * G4];
__device__ float g_Zh   [(size_t)B_SZ * G4];
__device__ float g_partX[(size_t)MB * G4 * 2];   // per-rowblock col (sum, sumsq)
__device__ float g_partH[(size_t)MB * G4 * 2];
__device__ float g_scX[G4], g_shX[G4], g_scH[G4], g_shH[G4];

// ---------------- helpers ------------------------------------------------------
__device__ __forceinline__ float sigm(float x) { return 1.f / (1.f + expf(-x)); }
__device__ __forceinline__ uint32_t packh2(float lo, float hi) {
    uint32_t r;
    asm("cvt.rn.f16x2.f32 %0, %1, %2;" : "=r"(r) : "f"(hi), "f"(lo));
    return r;
}
__device__ __forceinline__ void cpasync16(uint32_t dst, const void* src) {
    asm volatile("cp.async.cg.shared.global [%0], [%1], 16;\n" :: "r"(dst), "l"(src));
}

// ---------------- prep kernels: fp32 -> packed fp16 ----------------------------
__global__ void prep_h(const float* __restrict__ src, uint4* __restrict__ dst, int n8) {
    int t = blockIdx.x * blockDim.x + threadIdx.x;
    if (t >= n8) return;
    const float4* sp = (const float4*)(src + (size_t)t * 8);
    float4 a = sp[0], b = sp[1];
    dst[t] = make_uint4(packh2(a.x, a.y), packh2(a.z, a.w),
                        packh2(b.x, b.y), packh2(b.z, b.w));
}
__global__ void prep_inp_h(const float* __restrict__ x, const float* __restrict__ y) {
    int t = blockIdx.x * blockDim.x + threadIdx.x;     // B * 36
    if (t >= B_SZ * (KPAD / 8)) return;
    int b = t / (KPAD / 8), gi = t - b * (KPAD / 8);
    int j0 = gi * 8;
    float s[8];
    if (j0 < 256) {
        const float4* sp = (const float4*)(x + (size_t)b * 256 + j0);
        float4 a = sp[0], c = sp[1];
        s[0]=a.x; s[1]=a.y; s[2]=a.z; s[3]=a.w; s[4]=c.x; s[5]=c.y; s[6]=c.z; s[7]=c.w;
    } else {
#pragma unroll
        for (int i = 0; i < 8; i++) s[i] = 0.f;
        if (j0 == 256) s[0] = y[b];
    }
    g_inpH[t] = make_uint4(packh2(s[0], s[1]), packh2(s[2], s[3]),
                           packh2(s[4], s[5]), packh2(s[6], s[7]));
}
__global__ void prep_wx_h(const float* __restrict__ Wx) {
    int t = blockIdx.x * blockDim.x + threadIdx.x;     // G4 * 36
    if (t >= G4 * (KPAD / 8)) return;
    int r = t / (KPAD / 8), gi = t - r * (KPAD / 8);
    int j0 = gi * 8;
    float s[8];
#pragma unroll
    for (int i = 0; i < 8; i++) {
        int j = j0 + i;
        s[i] = (j < IN0) ? Wx[(size_t)r * IN0 + j] : 0.f;
    }
    g_WxH[t] = make_uint4(packh2(s[0], s[1]), packh2(s[2], s[3]),
                          packh2(s[4], s[5]), packh2(s[6], s[7]));
}

// ---------------- fp16 cp.async-pipelined GEMM: C = A * W^T (+bias) ------------
// block 128x128, BK=32 halves (64B/row + 16B pad = 80B stride), 3-stage ring,
// 8 warps (4x2), warp tile 32x64, mma m16n8k16 f16.f32. Fused BN-stats epilogue.
// Fragment banks: word idx = 20*r + w; for r = base+g: banks 20g+w distinct mod 32.
constexpr int SW = 20;                         // words per row (16 + 4 pad)
constexpr int STAGE_B = 2 * 128 * 80;          // bytes per stage (A + W) = 20480
constexpr int STAGE_W = STAGE_B / 4;           // words per stage = 5120
constexpr int SMEM_B = 3 * STAGE_B;            // 61440 bytes

__global__ __launch_bounds__(256, 2) void gemm_h(
    float* __restrict__ C, const __half* __restrict__ A, int lda,
    const __half* __restrict__ W, int ldw, int N, int K,
    const float* __restrict__ bias, float* __restrict__ part)
{
    extern __shared__ uint32_t sm[];
    const int tid  = threadIdx.x;
    const int lane = tid & 31, warp = tid >> 5;
    const int g    = lane >> 2, tg = lane & 3;
    const int wm   = warp >> 1, wn = warp & 1;
    const int mW   = wm * 32, nW = wn * 64;
    const int bM   = blockIdx.y * 128, bN = blockIdx.x * 128;
    const uint32_t smB = (uint32_t)__cvta_generic_to_shared(sm);

    float acc[2][8][4];
#pragma unroll
    for (int i = 0; i < 2; i++)
#pragma unroll
        for (int j = 0; j < 8; j++)
#pragma unroll
            for (int r = 0; r < 4; r++) acc[i][j][r] = 0.f;

    auto load_stage = [&](int it) {
        uint32_t base = smB + (uint32_t)(it % 3) * STAGE_B;
        int k0 = it << 5;
#pragma unroll
        for (int i = 0; i < 2; i++) {               // 512 chunks / 256 threads
            int u = tid + (i << 8);
            int row = u >> 2, ch = u & 3;           // 4 x 16B chunks per 64B row
            uint32_t d = base + (uint32_t)(row * 80 + ch * 16);
            cpasync16(d,          A + (size_t)(bM + row) * lda + k0 + ch * 8);
            cpasync16(d + 10240u, W + (size_t)(bN + row) * ldw + k0 + ch * 8);
        }
        asm volatile("cp.async.commit_group;\n");
    };

    const int nit = K >> 5;
    load_stage(0);
    if (nit > 1) load_stage(1);
    for (int it = 0; it < nit; ++it) {
        if (it + 1 < nit) asm volatile("cp.async.wait_group 1;\n" ::: "memory");
        else              asm volatile("cp.async.wait_group 0;\n" ::: "memory");
        __syncthreads();                      // stage(it) visible; stage(it-1) consumed
        if (it + 2 < nit) load_stage(it + 2); // overwrites stage consumed at it-1
        const uint32_t* sA = sm + (it % 3) * STAGE_W;
        const uint32_t* sW = sA + 2560;
#pragma unroll
        for (int ks = 0; ks < 2; ks++) {
            const int wb = ks * 8;
            uint32_t a[2][4], b[8][2];
#pragma unroll
            for (int mt = 0; mt < 2; mt++) {
                int r0 = mW + mt * 16 + g;
                a[mt][0] = sA[(r0    ) * SW + wb + tg];
                a[mt][1] = sA[(r0 + 8) * SW + wb + tg];
                a[mt][2] = sA[(r0    ) * SW + wb + tg + 4];
                a[mt][3] = sA[(r0 + 8) * SW + wb + tg + 4];
            }
#pragma unroll
            for (int nt = 0; nt < 8; nt++) {
                int rn = nW + nt * 8 + g;
                b[nt][0] = sW[rn * SW + wb + tg];
                b[nt][1] = sW[rn * SW + wb + tg + 4];
            }
#pragma unroll
            for (int mt = 0; mt < 2; mt++)
#pragma unroll
                for (int nt = 0; nt < 8; nt++)
                    asm volatile(
                        "mma.sync.aligned.m16n8k16.row.col.f32.f16.f16.f32 "
                        "{%0,%1,%2,%3},{%4,%5,%6,%7},{%8,%9},{%0,%1,%2,%3};\n"
                        : "+f"(acc[mt][nt][0]), "+f"(acc[mt][nt][1]),
                          "+f"(acc[mt][nt][2]), "+f"(acc[mt][nt][3])
                        : "r"(a[mt][0]), "r"(a[mt][1]), "r"(a[mt][2]), "r"(a[mt][3]),
                          "r"(b[nt][0]), "r"(b[nt][1]));
        }
    }

    // ---- C-tile writeback ----
#pragma unroll
    for (int mt = 0; mt < 2; mt++) {
        int r0 = bM + mW + mt * 16 + g;
#pragma unroll
        for (int nt = 0; nt < 8; nt++) {
            int c = bN + nW + nt * 8 + 2 * tg;
            float b0 = 0.f, b1 = 0.f;
            if (bias) { b0 = bias[c]; b1 = bias[c + 1]; }
            *(float2*)(C + (size_t)r0 * N + c)       = make_float2(acc[mt][nt][0] + b0, acc[mt][nt][1] + b1);
            *(float2*)(C + (size_t)(r0 + 8) * N + c) = make_float2(acc[mt][nt][2] + b0, acc[mt][nt][3] + b1);
        }
    }

    // ---- fused BN statistics: per-block column (sum, sumsq) partials ----
    if (part) {
        __syncthreads();                       // compute done; reuse stage smem
        float* psm = (float*)sm;               // [4 wm][128 col][2]
#pragma unroll
        for (int nt = 0; nt < 8; nt++) {
            float s0 = 0.f, q0 = 0.f, s1 = 0.f, q1 = 0.f;
#pragma unroll
            for (int mt = 0; mt < 2; mt++) {
                float v0 = acc[mt][nt][0], v2 = acc[mt][nt][2];
                float v1 = acc[mt][nt][1], v3 = acc[mt][nt][3];
                s0 += v0 + v2; q0 += v0 * v0 + v2 * v2;
                s1 += v1 + v3; q1 += v1 * v1 + v3 * v3;
            }
#pragma unroll
            for (int off = 16; off >= 4; off >>= 1) {
                s0 += __shfl_xor_sync(0xFFFFFFFFu, s0, off);
                q0 += __shfl_xor_sync(0xFFFFFFFFu, q0, off);
                s1 += __shfl_xor_sync(0xFFFFFFFFu, s1, off);
                q1 += __shfl_xor_sync(0xFFFFFFFFu, q1, off);
            }
            if (g == 0) {
                int col = nW + nt * 8 + 2 * tg;
                psm[(wm * 128 + col) * 2 + 0]     = s0;
                psm[(wm * 128 + col) * 2 + 1]     = q0;
                psm[(wm * 128 + col + 1) * 2 + 0] = s1;
                psm[(wm * 128 + col + 1) * 2 + 1] = q1;
            }
        }
        __syncthreads();
        {
            int col = tid >> 1, sq = tid & 1;
            float v = psm[(col) * 2 + sq] + psm[(128 + col) * 2 + sq]
                    + psm[(256 + col) * 2 + sq] + psm[(384 + col) * 2 + sq];
            part[((size_t)blockIdx.y * N + bN + col) * 2 + sq] = v;
        }
    }
}

// ---------------- fold partials into BN affine scale/shift ---------------------
__global__ void stats_final(const float* __restrict__ gx, const float* __restrict__ bx,
                            const float* __restrict__ gh, const float* __restrict__ bh) {
    int j = blockIdx.x * blockDim.x + threadIdx.x;     // 2048
    float sx = 0.f, qx = 0.f, sh = 0.f, qh = 0.f;
    for (int rb = 0; rb < MB; rb++) {
        size_t o = ((size_t)rb * G4 + j) * 2;
        sx += g_partX[o]; qx += g_partX[o + 1];
        sh += g_partH[o]; qh += g_partH[o + 1];
    }
    const float invB = 1.f / (float)B_SZ;
    float mx = sx * invB, vx = qx * invB - mx * mx;
    float ax = gx[j] * rsqrtf(vx + 1e-5f);
    g_scX[j] = ax; g_shX[j] = bx[j] - mx * ax;
    float mh = sh * invB, vh = qh * invB - mh * mh;
    float ah = gh[j] * rsqrtf(vh + 1e-5f);
    g_scH[j] = ah; g_shH[j] = bh[j] - mh * ah;
}

// ---------------- fused BN + LSTM cell + fp16 h export -------------------------
__global__ void cell_kernel(const float* __restrict__ Zx, const float* __restrict__ Zh,
                            const float* __restrict__ cPrev,
                            float* __restrict__ hOut, uint2* __restrict__ hT,
                            float* __restrict__ cOut) {
    int t = blockIdx.x * blockDim.x + threadIdx.x;     // B*128 threads
    int jv = t & 127, b = t >> 7;                      // jv: float4 index in 512
    size_t base4 = ((size_t)b << 9) + jv;
    const float4* zx = (const float4*)Zx;
    const float4* zh = (const float4*)Zh;
    float4 zf4 = zx[base4      ], hf4 = zh[base4      ];
    float4 zi4 = zx[base4 + 128], hi4 = zh[base4 + 128];
    float4 zo4 = zx[base4 + 256], ho4 = zh[base4 + 256];
    float4 zg4 = zx[base4 + 384], hg4 = zh[base4 + 384];
    const float4* scX = (const float4*)g_scX; const float4* shX = (const float4*)g_shX;
    const float4* scH = (const float4*)g_scH; const float4* shH = (const float4*)g_shH;
    float4 sxf = scX[jv], txf = shX[jv], shf = scH[jv], thf = shH[jv];
    float4 sxi = scX[jv + 128], txi = shX[jv + 128], shi = scH[jv + 128], thi = shH[jv + 128];
    float4 sxo = scX[jv + 256], txo = shX[jv + 256], sho = scH[jv + 256], tho = shH[jv + 256];
    float4 sxg = scX[jv + 384], txg = shX[jv + 384], shg = scH[jv + 384], thg = shH[jv + 384];
    float4 cp = ((const float4*)cPrev)[((size_t)b << 7) + jv];

    float zf[4] = { zf4.x*sxf.x+txf.x + hf4.x*shf.x+thf.x, zf4.y*sxf.y+txf.y + hf4.y*shf.y+thf.y,
                    zf4.z*sxf.z+txf.z + hf4.z*shf.z+thf.z, zf4.w*sxf.w+txf.w + hf4.w*shf.w+thf.w };
    float zi[4] = { zi4.x*sxi.x+txi.x + hi4.x*shi.x+thi.x, zi4.y*sxi.y+txi.y + hi4.y*shi.y+thi.y,
                    zi4.z*sxi.z+txi.z + hi4.z*shi.z+thi.z, zi4.w*sxi.w+txi.w + hi4.w*shi.w+thi.w };
    float zo[4] = { zo4.x*sxo.x+txo.x + ho4.x*sho.x+tho.x, zo4.y*sxo.y+txo.y + ho4.y*sho.y+tho.y,
                    zo4.z*sxo.z+txo.z + ho4.z*sho.z+tho.z, zo4.w*sxo.w+txo.w + ho4.w*sho.w+tho.w };
    float zg[4] = { zg4.x*sxg.x+txg.x + hg4.x*shg.x+thg.x, zg4.y*sxg.y+txg.y + hg4.y*shg.y+thg.y,
                    zg4.z*sxg.z+txg.z + hg4.z*shg.z+thg.z, zg4.w*sxg.w+txg.w + hg4.w*shg.w+thg.w };
    float cpv[4] = { cp.x, cp.y, cp.z, cp.w };
    float h[4], c[4];
#pragma unroll
    for (int i = 0; i < 4; i++) {
        c[i] = sigm(zf[i]) * cpv[i] + sigm(zi[i]) * tanhf(zg[i]);
        h[i] = sigm(zo[i]) * tanhf(c[i]);
    }
    ((float4*)hOut)[((size_t)b << 7) + jv] = make_float4(h[0], h[1], h[2], h[3]);
    ((float4*)cOut)[((size_t)b << 7) + jv] = make_float4(c[0], c[1], c[2], c[3]);
    hT[((size_t)b << 7) + jv] = make_uint2(packh2(h[0], h[1]), packh2(h[2], h[3]));
}

// ---------------- launch -------------------------------------------------------
extern "C" void kernel_launch(void* const* d_in, const int* in_sizes, int n_in,
                              void* d_out, int out_size) {
    const float* x   = (const float*)d_in[0];
    const float* y   = (const float*)d_in[1];
    const float* h0  = (const float*)d_in[2];
    const float* c0  = (const float*)d_in[3];
    const float* Wx0 = (const float*)d_in[4];
    const float* Wh0 = (const float*)d_in[5];
    const float* gx0 = (const float*)d_in[6];
    const float* bx0 = (const float*)d_in[7];
    const float* gh0 = (const float*)d_in[8];
    const float* bh0 = (const float*)d_in[9];
    const float* Wx1 = (const float*)d_in[10];
    const float* Wh1 = (const float*)d_in[11];
    const float* gx1 = (const float*)d_in[12];
    const float* bx1 = (const float*)d_in[13];
    const float* gh1 = (const float*)d_in[14];
    const float* bh1 = (const float*)d_in[15];
    const float* Wo  = (const float*)d_in[16];
    const float* bo  = (const float*)d_in[17];
    float* out = (float*)d_out;

    cudaFuncSetAttribute(gemm_h, cudaFuncAttributeMaxDynamicSharedMemorySize, SMEM_B);

    void *inpH, *wxH, *h00H, *h01H, *h1H, *h2H, *wh0H, *wx1H, *wh1H, *woH;
    float *Zx, *Zh, *partX, *partH;
    cudaGetSymbolAddress(&inpH, g_inpH);
    cudaGetSymbolAddress(&wxH,  g_WxH);
    cudaGetSymbolAddress(&h00H, g_h00H);
    cudaGetSymbolAddress(&h01H, g_h01H);
    cudaGetSymbolAddress(&h1H,  g_h1H);
    cudaGetSymbolAddress(&h2H,  g_h2H);
    cudaGetSymbolAddress(&wh0H, g_Wh0H);
    cudaGetSymbolAddress(&wx1H, g_Wx1H);
    cudaGetSymbolAddress(&wh1H, g_Wh1H);
    cudaGetSymbolAddress(&woH,  g_WoH);
    cudaGetSymbolAddress((void**)&Zx,    g_Zx);
    cudaGetSymbolAddress((void**)&Zh,    g_Zh);
    cudaGetSymbolAddress((void**)&partX, g_partX);
    cudaGetSymbolAddress((void**)&partH, g_partH);

    // output layout: out[B,256], h1[B,512], h2[B,512], c1[B,512], c2[B,512]
    float* h1 = out + (size_t)B_SZ * OUTF;
    float* h2 = h1 + (size_t)B_SZ * H_SZ;
    float* c1 = h2 + (size_t)B_SZ * H_SZ;
    float* c2 = c1 + (size_t)B_SZ * H_SZ;
    const float* h00 = h0;
    const float* h01 = h0 + (size_t)B_SZ * H_SZ;
    const float* c00 = c0;
    const float* c01 = c0 + (size_t)B_SZ * H_SZ;

    const int BH = B_SZ * H_SZ;
    const int GH = G4 * H_SZ;

    // operand conversion to fp16
    prep_inp_h<<<(B_SZ * (KPAD / 8) + 255) / 256, 256>>>(x, y);
    prep_wx_h<<<(G4 * (KPAD / 8) + 255) / 256, 256>>>(Wx0);
    prep_h<<<(BH / 8 + 255) / 256, 256>>>(h00, (uint4*)h00H, BH / 8);
    prep_h<<<(BH / 8 + 255) / 256, 256>>>(h01, (uint4*)h01H, BH / 8);
    prep_h<<<(GH / 8 + 255) / 256, 256>>>(Wh0, (uint4*)wh0H, GH / 8);
    prep_h<<<(GH / 8 + 255) / 256, 256>>>(Wx1, (uint4*)wx1H, GH / 8);
    prep_h<<<(GH / 8 + 255) / 256, 256>>>(Wh1, (uint4*)wh1H, GH / 8);
    prep_h<<<(OUTF * H_SZ / 8 + 255) / 256, 256>>>(Wo, (uint4*)woH, OUTF * H_SZ / 8);

    dim3 gg(G4 / 128, B_SZ / 128);     // 16 x 128
    dim3 go(OUTF / 128, B_SZ / 128);   // 2 x 128

    // layer 0
    gemm_h<<<gg, 256, SMEM_B>>>(Zx, (const __half*)inpH, KPAD, (const __half*)wxH, KPAD,
                                G4, KPAD, nullptr, partX);
    gemm_h<<<gg, 256, SMEM_B>>>(Zh, (const __half*)h00H, H_SZ, (const __half*)wh0H, H_SZ,
                                G4, H_SZ, nullptr, partH);
    stats_final<<<G4 / 256, 256>>>(gx0, bx0, gh0, bh0);
    cell_kernel<<<BH / 4 / 256, 256>>>(Zx, Zh, c00, h1, (uint2*)h1H, c1);

    // layer 1
    gemm_h<<<gg, 256, SMEM_B>>>(Zx, (const __half*)h1H, H_SZ, (const __half*)wx1H, H_SZ,
                                G4, H_SZ, nullptr, partX);
    gemm_h<<<gg, 256, SMEM_B>>>(Zh, (const __half*)h01H, H_SZ, (const __half*)wh1H, H_SZ,
                                G4, H_SZ, nullptr, partH);
    stats_final<<<G4 / 256, 256>>>(gx1, bx1, gh1, bh1);
    cell_kernel<<<BH / 4 / 256, 256>>>(Zx, Zh, c01, h2, (uint2*)h2H, c2);

    // output projection (no stats)
    gemm_h<<<go, 256, SMEM_B>>>(out, (const __half*)h2H, H_SZ, (const __half*)woH, H_SZ,
                                OUTF, H_SZ, bo, nullptr);
}

// round 17
// speedup vs baseline: 1.8852x; 1.1033x over previous
#include <cuda_runtime.h>
#include <cuda_fp16.h>
#include <cstdint>
#include <math.h>

#define B_SZ 16384
#define H_SZ 512
#define G4   2048
#define OUTF 256
#define KPAD 320          // 257 padded to multiple of 64
#define IN0  257
#define MB   128          // row-blocks along batch = B/128

// ---------------- scratch (static device memory) ------------------------------
__device__ __align__(16) uint4 g_inpH [(size_t)B_SZ * (KPAD / 8)];
__device__ __align__(16) uint4 g_WxH  [(size_t)G4 * (KPAD / 8)];
__device__ __align__(16) uint4 g_h00H [(size_t)B_SZ * (H_SZ / 8)];
__device__ __align__(16) uint4 g_h01H [(size_t)B_SZ * (H_SZ / 8)];
__device__ __align__(16) uint4 g_h1H  [(size_t)B_SZ * (H_SZ / 8)];
__device__ __align__(16) uint4 g_h2H  [(size_t)B_SZ * (H_SZ / 8)];
__device__ __align__(16) uint4 g_Wh0H [(size_t)G4 * (H_SZ / 8)];
__device__ __align__(16) uint4 g_Wx1H [(size_t)G4 * (H_SZ / 8)];
__device__ __align__(16) uint4 g_Wh1H [(size_t)G4 * (H_SZ / 8)];
__device__ __align__(16) uint4 g_WoH  [(size_t)OUTF * (H_SZ / 8)];
__device__ __align__(16) uint32_t g_ZxH[(size_t)B_SZ * G4 / 2];   // fp16 gates
__device__ __align__(16) uint32_t g_ZhH[(size_t)B_SZ * G4 / 2];
__device__ float g_partX[(size_t)MB * G4 * 2];   // per-rowblock col (sum, sumsq)
__device__ float g_partH[(size_t)MB * G4 * 2];
__device__ float g_scX[G4], g_shX[G4], g_scH[G4], g_shH[G4];

// ---------------- helpers ------------------------------------------------------
__device__ __forceinline__ float sigm(float x) { return 1.f / (1.f + expf(-x)); }
__device__ __forceinline__ uint32_t packh2(float lo, float hi) {
    uint32_t r;
    asm("cvt.rn.f16x2.f32 %0, %1, %2;" : "=r"(r) : "f"(hi), "f"(lo));
    return r;
}
__device__ __forceinline__ float2 unpackh2(uint32_t v) {
    __half2 h = *(__half2*)&v;
    return __half22float2(h);
}
__device__ __forceinline__ void cpasync16(uint32_t dst, const void* src) {
    asm volatile("cp.async.cg.shared.global [%0], [%1], 16;\n" :: "r"(dst), "l"(src));
}

// ---------------- prep kernels: fp32 -> packed fp16 ----------------------------
__global__ void prep_h(const float* __restrict__ src, uint4* __restrict__ dst, int n8) {
    int t = blockIdx.x * blockDim.x + threadIdx.x;
    if (t >= n8) return;
    const float4* sp = (const float4*)(src + (size_t)t * 8);
    float4 a = sp[0], b = sp[1];
    dst[t] = make_uint4(packh2(a.x, a.y), packh2(a.z, a.w),
                        packh2(b.x, b.y), packh2(b.z, b.w));
}
__global__ void prep_inp_h(const float* __restrict__ x, const float* __restrict__ y) {
    int t = blockIdx.x * blockDim.x + threadIdx.x;     // B * 40
    if (t >= B_SZ * (KPAD / 8)) return;
    int b = t / (KPAD / 8), gi = t - b * (KPAD / 8);
    int j0 = gi * 8;
    float s[8];
    if (j0 < 256) {
        const float4* sp = (const float4*)(x + (size_t)b * 256 + j0);
        float4 a = sp[0], c = sp[1];
        s[0]=a.x; s[1]=a.y; s[2]=a.z; s[3]=a.w; s[4]=c.x; s[5]=c.y; s[6]=c.z; s[7]=c.w;
    } else {
#pragma unroll
        for (int i = 0; i < 8; i++) s[i] = 0.f;
        if (j0 == 256) s[0] = y[b];
    }
    g_inpH[t] = make_uint4(packh2(s[0], s[1]), packh2(s[2], s[3]),
                           packh2(s[4], s[5]), packh2(s[6], s[7]));
}
__global__ void prep_wx_h(const float* __restrict__ Wx) {
    int t = blockIdx.x * blockDim.x + threadIdx.x;     // G4 * 40
    if (t >= G4 * (KPAD / 8)) return;
    int r = t / (KPAD / 8), gi = t - r * (KPAD / 8);
    int j0 = gi * 8;
    float s[8];
#pragma unroll
    for (int i = 0; i < 8; i++) {
        int j = j0 + i;
        s[i] = (j < IN0) ? Wx[(size_t)r * IN0 + j] : 0.f;
    }
    g_WxH[t] = make_uint4(packh2(s[0], s[1]), packh2(s[2], s[3]),
                          packh2(s[4], s[5]), packh2(s[6], s[7]));
}

// ---------------- fp16 cp.async-pipelined GEMM -----------------------------------
// block 128x128, BK=64 halves (128B/row + 16B pad = 144B stride), 3-stage ring,
// 8 warps (4x2), warp tile 32x64, mma m16n8k16 f16.f32, fused BN-stats epilogue.
// Output: half (Ch != null) or float+bias (Cf).
constexpr int SWW = 36;                        // words per row (32 + 4 pad)
constexpr int STAGE_B = 2 * 128 * 144;         // bytes per stage = 36864
constexpr int STAGE_W = STAGE_B / 4;           // 9216 words
constexpr int HALF_W  = STAGE_W / 2;           // 4608 words (A|W split)
constexpr int SMEM_B  = 3 * STAGE_B;           // 110592 bytes

__global__ __launch_bounds__(256, 2) void gemm_h(
    float* __restrict__ Cf, uint32_t* __restrict__ Ch,
    const __half* __restrict__ A, int lda,
    const __half* __restrict__ W, int ldw, int N, int K,
    const float* __restrict__ bias, float* __restrict__ part)
{
    extern __shared__ uint32_t sm[];
    const int tid  = threadIdx.x;
    const int lane = tid & 31, warp = tid >> 5;
    const int g    = lane >> 2, tg = lane & 3;
    const int wm   = warp >> 1, wn = warp & 1;
    const int mW   = wm * 32, nW = wn * 64;
    const int bM   = blockIdx.y * 128, bN = blockIdx.x * 128;
    const uint32_t smB = (uint32_t)__cvta_generic_to_shared(sm);

    float acc[2][8][4];
#pragma unroll
    for (int i = 0; i < 2; i++)
#pragma unroll
        for (int j = 0; j < 8; j++)
#pragma unroll
            for (int r = 0; r < 4; r++) acc[i][j][r] = 0.f;

    auto load_stage = [&](int it) {
        uint32_t base = smB + (uint32_t)(it % 3) * STAGE_B;
        int k0 = it << 6;
#pragma unroll
        for (int i = 0; i < 8; i++) {               // 2048 x 16B chunks / 256 thr
            int u = tid + (i << 8);
            int arr = u >> 10, row = (u >> 3) & 127, ch = u & 7;
            uint32_t d = base + (uint32_t)(arr * 18432 + row * 144 + ch * 16);
            const __half* src = arr ? (W + (size_t)(bN + row) * ldw + k0 + ch * 8)
                                    : (A + (size_t)(bM + row) * lda + k0 + ch * 8);
            cpasync16(d, src);
        }
        asm volatile("cp.async.commit_group;\n");
    };

    const int nit = K >> 6;
    load_stage(0);
    if (nit > 1) load_stage(1);
    for (int it = 0; it < nit; ++it) {
        if (it + 1 < nit) asm volatile("cp.async.wait_group 1;\n" ::: "memory");
        else              asm volatile("cp.async.wait_group 0;\n" ::: "memory");
        __syncthreads();
        if (it + 2 < nit) load_stage(it + 2);
        const uint32_t* sA = sm + (it % 3) * STAGE_W;
        const uint32_t* sW = sA + HALF_W;
#pragma unroll
        for (int ks = 0; ks < 4; ks++) {
            const int wb = ks * 8;
            uint32_t a[2][4], b[8][2];
#pragma unroll
            for (int mt = 0; mt < 2; mt++) {
                int r0 = mW + mt * 16 + g;
                a[mt][0] = sA[(r0    ) * SWW + wb + tg];
                a[mt][1] = sA[(r0 + 8) * SWW + wb + tg];
                a[mt][2] = sA[(r0    ) * SWW + wb + tg + 4];
                a[mt][3] = sA[(r0 + 8) * SWW + wb + tg + 4];
            }
#pragma unroll
            for (int nt = 0; nt < 8; nt++) {
                int rn = nW + nt * 8 + g;
                b[nt][0] = sW[rn * SWW + wb + tg];
                b[nt][1] = sW[rn * SWW + wb + tg + 4];
            }
#pragma unroll
            for (int mt = 0; mt < 2; mt++)
#pragma unroll
                for (int nt = 0; nt < 8; nt++)
                    asm volatile(
                        "mma.sync.aligned.m16n8k16.row.col.f32.f16.f16.f32 "
                        "{%0,%1,%2,%3},{%4,%5,%6,%7},{%8,%9},{%0,%1,%2,%3};\n"
                        : "+f"(acc[mt][nt][0]), "+f"(acc[mt][nt][1]),
                          "+f"(acc[mt][nt][2]), "+f"(acc[mt][nt][3])
                        : "r"(a[mt][0]), "r"(a[mt][1]), "r"(a[mt][2]), "r"(a[mt][3]),
                          "r"(b[nt][0]), "r"(b[nt][1]));
        }
    }

    // ---- C-tile writeback: half (scratch gates) or float+bias (final out) ----
    if (Ch) {
        const int N2 = N >> 1;
#pragma unroll
        for (int mt = 0; mt < 2; mt++) {
            int r0 = bM + mW + mt * 16 + g;
#pragma unroll
            for (int nt = 0; nt < 8; nt++) {
                int c = bN + nW + nt * 8 + 2 * tg;
                Ch[(size_t)r0 * N2 + (c >> 1)]       = packh2(acc[mt][nt][0], acc[mt][nt][1]);
                Ch[(size_t)(r0 + 8) * N2 + (c >> 1)] = packh2(acc[mt][nt][2], acc[mt][nt][3]);
            }
        }
    } else {
#pragma unroll
        for (int mt = 0; mt < 2; mt++) {
            int r0 = bM + mW + mt * 16 + g;
#pragma unroll
            for (int nt = 0; nt < 8; nt++) {
                int c = bN + nW + nt * 8 + 2 * tg;
                float b0 = bias ? bias[c] : 0.f;
                float b1 = bias ? bias[c + 1] : 0.f;
                *(float2*)(Cf + (size_t)r0 * N + c)       = make_float2(acc[mt][nt][0] + b0, acc[mt][nt][1] + b1);
                *(float2*)(Cf + (size_t)(r0 + 8) * N + c) = make_float2(acc[mt][nt][2] + b0, acc[mt][nt][3] + b1);
            }
        }
    }

    // ---- fused BN statistics from fp32 accumulators ----
    if (part) {
        __syncthreads();
        float* psm = (float*)sm;               // [4 wm][128 col][2]
#pragma unroll
        for (int nt = 0; nt < 8; nt++) {
            float s0 = 0.f, q0 = 0.f, s1 = 0.f, q1 = 0.f;
#pragma unroll
            for (int mt = 0; mt < 2; mt++) {
                float v0 = acc[mt][nt][0], v2 = acc[mt][nt][2];
                float v1 = acc[mt][nt][1], v3 = acc[mt][nt][3];
                s0 += v0 + v2; q0 += v0 * v0 + v2 * v2;
                s1 += v1 + v3; q1 += v1 * v1 + v3 * v3;
            }
#pragma unroll
            for (int off = 16; off >= 4; off >>= 1) {
                s0 += __shfl_xor_sync(0xFFFFFFFFu, s0, off);
                q0 += __shfl_xor_sync(0xFFFFFFFFu, q0, off);
                s1 += __shfl_xor_sync(0xFFFFFFFFu, s1, off);
                q1 += __shfl_xor_sync(0xFFFFFFFFu, q1, off);
            }
            if (g == 0) {
                int col = nW + nt * 8 + 2 * tg;
                psm[(wm * 128 + col) * 2 + 0]     = s0;
                psm[(wm * 128 + col) * 2 + 1]     = q0;
                psm[(wm * 128 + col + 1) * 2 + 0] = s1;
                psm[(wm * 128 + col + 1) * 2 + 1] = q1;
            }
        }
        __syncthreads();
        {
            int col = tid >> 1, sq = tid & 1;
            float v = psm[(col) * 2 + sq] + psm[(128 + col) * 2 + sq]
                    + psm[(256 + col) * 2 + sq] + psm[(384 + col) * 2 + sq];
            part[((size_t)blockIdx.y * N + bN + col) * 2 + sq] = v;
        }
    }
}

// ---------------- fold partials into BN affine scale/shift ---------------------
__global__ void stats_final(const float* __restrict__ gx, const float* __restrict__ bx,
                            const float* __restrict__ gh, const float* __restrict__ bh) {
    int j = blockIdx.x * blockDim.x + threadIdx.x;     // 2048
    float sx = 0.f, qx = 0.f, sh = 0.f, qh = 0.f;
    for (int rb = 0; rb < MB; rb++) {
        size_t o = ((size_t)rb * G4 + j) * 2;
        sx += g_partX[o]; qx += g_partX[o + 1];
        sh += g_partH[o]; qh += g_partH[o + 1];
    }
    const float invB = 1.f / (float)B_SZ;
    float mx = sx * invB, vx = qx * invB - mx * mx;
    float ax = gx[j] * rsqrtf(vx + 1e-5f);
    g_scX[j] = ax; g_shX[j] = bx[j] - mx * ax;
    float mh = sh * invB, vh = qh * invB - mh * mh;
    float ah = gh[j] * rsqrtf(vh + 1e-5f);
    g_scH[j] = ah; g_shH[j] = bh[j] - mh * ah;
}

// ---------------- fused BN + LSTM cell (fp16 Z in, fp32 + fp16 h out) ----------
__global__ void cell_kernel(const uint2* __restrict__ ZxH, const uint2* __restrict__ ZhH,
                            const float* __restrict__ cPrev,
                            float* __restrict__ hOut, uint2* __restrict__ hT,
                            float* __restrict__ cOut) {
    int t = blockIdx.x * blockDim.x + threadIdx.x;     // B*128 threads
    int jv = t & 127, b = t >> 7;                      // jv: 4-col group in 512
    size_t base = ((size_t)b << 9) + jv;               // uint2 units (4 halves each)
    uint2 zfu = ZxH[base      ], hfu = ZhH[base      ];
    uint2 ziu = ZxH[base + 128], hiu = ZhH[base + 128];
    uint2 zou = ZxH[base + 256], hou = ZhH[base + 256];
    uint2 zgu = ZxH[base + 384], hgu = ZhH[base + 384];
    const float4* scX = (const float4*)g_scX; const float4* shX = (const float4*)g_shX;
    const float4* scH = (const float4*)g_scH; const float4* shH = (const float4*)g_shH;
    float4 sxf = scX[jv], txf = shX[jv], shf = scH[jv], thf = shH[jv];
    float4 sxi = scX[jv + 128], txi = shX[jv + 128], shi = scH[jv + 128], thi = shH[jv + 128];
    float4 sxo = scX[jv + 256], txo = shX[jv + 256], sho = scH[jv + 256], tho = shH[jv + 256];
    float4 sxg = scX[jv + 384], txg = shX[jv + 384], shg = scH[jv + 384], thg = shH[jv + 384];
    float4 cp = ((const float4*)cPrev)[((size_t)b << 7) + jv];

    float2 zf0 = unpackh2(zfu.x), zf1 = unpackh2(zfu.y), hf0 = unpackh2(hfu.x), hf1 = unpackh2(hfu.y);
    float2 zi0 = unpackh2(ziu.x), zi1 = unpackh2(ziu.y), hi0 = unpackh2(hiu.x), hi1 = unpackh2(hiu.y);
    float2 zo0 = unpackh2(zou.x), zo1 = unpackh2(zou.y), ho0 = unpackh2(hou.x), ho1 = unpackh2(hou.y);
    float2 zg0 = unpackh2(zgu.x), zg1 = unpackh2(zgu.y), hg0 = unpackh2(hgu.x), hg1 = unpackh2(hgu.y);

    float zf[4] = { zf0.x*sxf.x+txf.x + hf0.x*shf.x+thf.x, zf0.y*sxf.y+txf.y + hf0.y*shf.y+thf.y,
                    zf1.x*sxf.z+txf.z + hf1.x*shf.z+thf.z, zf1.y*sxf.w+txf.w + hf1.y*shf.w+thf.w };
    float zi[4] = { zi0.x*sxi.x+txi.x + hi0.x*shi.x+thi.x, zi0.y*sxi.y+txi.y + hi0.y*shi.y+thi.y,
                    zi1.x*sxi.z+txi.z + hi1.x*shi.z+thi.z, zi1.y*sxi.w+txi.w + hi1.y*shi.w+thi.w };
    float zo[4] = { zo0.x*sxo.x+txo.x + ho0.x*sho.x+tho.x, zo0.y*sxo.y+txo.y + ho0.y*sho.y+tho.y,
                    zo1.x*sxo.z+txo.z + ho1.x*sho.z+tho.z, zo1.y*sxo.w+txo.w + ho1.y*sho.w+tho.w };
    float zg[4] = { zg0.x*sxg.x+txg.x + hg0.x*shg.x+thg.x, zg0.y*sxg.y+txg.y + hg0.y*shg.y+thg.y,
                    zg1.x*sxg.z+txg.z + hg1.x*shg.z+thg.z, zg1.y*sxg.w+txg.w + hg1.y*shg.w+thg.w };
    float cpv[4] = { cp.x, cp.y, cp.z, cp.w };
    float h[4], c[4];
#pragma unroll
    for (int i = 0; i < 4; i++) {
        c[i] = sigm(zf[i]) * cpv[i] + sigm(zi[i]) * tanhf(zg[i]);
        h[i] = sigm(zo[i]) * tanhf(c[i]);
    }
    ((float4*)hOut)[((size_t)b << 7) + jv] = make_float4(h[0], h[1], h[2], h[3]);
    ((float4*)cOut)[((size_t)b << 7) + jv] = make_float4(c[0], c[1], c[2], c[3]);
    hT[((size_t)b << 7) + jv] = make_uint2(packh2(h[0], h[1]), packh2(h[2], h[3]));
}

// ---------------- launch -------------------------------------------------------
extern "C" void kernel_launch(void* const* d_in, const int* in_sizes, int n_in,
                              void* d_out, int out_size) {
    const float* x   = (const float*)d_in[0];
    const float* y   = (const float*)d_in[1];
    const float* h0  = (const float*)d_in[2];
    const float* c0  = (const float*)d_in[3];
    const float* Wx0 = (const float*)d_in[4];
    const float* Wh0 = (const float*)d_in[5];
    const float* gx0 = (const float*)d_in[6];
    const float* bx0 = (const float*)d_in[7];
    const float* gh0 = (const float*)d_in[8];
    const float* bh0 = (const float*)d_in[9];
    const float* Wx1 = (const float*)d_in[10];
    const float* Wh1 = (const float*)d_in[11];
    const float* gx1 = (const float*)d_in[12];
    const float* bx1 = (const float*)d_in[13];
    const float* gh1 = (const float*)d_in[14];
    const float* bh1 = (const float*)d_in[15];
    const float* Wo  = (const float*)d_in[16];
    const float* bo  = (const float*)d_in[17];
    float* out = (float*)d_out;

    cudaFuncSetAttribute(gemm_h, cudaFuncAttributeMaxDynamicSharedMemorySize, SMEM_B);

    void *inpH, *wxH, *h00H, *h01H, *h1H, *h2H, *wh0H, *wx1H, *wh1H, *woH, *ZxH, *ZhH;
    float *partX, *partH;
    cudaGetSymbolAddress(&inpH, g_inpH);
    cudaGetSymbolAddress(&wxH,  g_WxH);
    cudaGetSymbolAddress(&h00H, g_h00H);
    cudaGetSymbolAddress(&h01H, g_h01H);
    cudaGetSymbolAddress(&h1H,  g_h1H);
    cudaGetSymbolAddress(&h2H,  g_h2H);
    cudaGetSymbolAddress(&wh0H, g_Wh0H);
    cudaGetSymbolAddress(&wx1H, g_Wx1H);
    cudaGetSymbolAddress(&wh1H, g_Wh1H);
    cudaGetSymbolAddress(&woH,  g_WoH);
    cudaGetSymbolAddress(&ZxH,  g_ZxH);
    cudaGetSymbolAddress(&ZhH,  g_ZhH);
    cudaGetSymbolAddress((void**)&partX, g_partX);
    cudaGetSymbolAddress((void**)&partH, g_partH);

    // output layout: out[B,256], h1[B,512], h2[B,512], c1[B,512], c2[B,512]
    float* h1 = out + (size_t)B_SZ * OUTF;
    float* h2 = h1 + (size_t)B_SZ * H_SZ;
    float* c1 = h2 + (size_t)B_SZ * H_SZ;
    float* c2 = c1 + (size_t)B_SZ * H_SZ;
    const float* h00 = h0;
    const float* h01 = h0 + (size_t)B_SZ * H_SZ;
    const float* c00 = c0;
    const float* c01 = c0 + (size_t)B_SZ * H_SZ;

    const int BH = B_SZ * H_SZ;
    const int GH = G4 * H_SZ;

    // operand conversion to fp16
    prep_inp_h<<<(B_SZ * (KPAD / 8) + 255) / 256, 256>>>(x, y);
    prep_wx_h<<<(G4 * (KPAD / 8) + 255) / 256, 256>>>(Wx0);
    prep_h<<<(BH / 8 + 255) / 256, 256>>>(h00, (uint4*)h00H, BH / 8);
    prep_h<<<(BH / 8 + 255) / 256, 256>>>(h01, (uint4*)h01H, BH / 8);
    prep_h<<<(GH / 8 + 255) / 256, 256>>>(Wh0, (uint4*)wh0H, GH / 8);
    prep_h<<<(GH / 8 + 255) / 256, 256>>>(Wx1, (uint4*)wx1H, GH / 8);
    prep_h<<<(GH / 8 + 255) / 256, 256>>>(Wh1, (uint4*)wh1H, GH / 8);
    prep_h<<<(OUTF * H_SZ / 8 + 255) / 256, 256>>>(Wo, (uint4*)woH, OUTF * H_SZ / 8);

    dim3 gg(G4 / 128, B_SZ / 128);     // 16 x 128
    dim3 go(OUTF / 128, B_SZ / 128);   // 2 x 128

    // layer 0
    gemm_h<<<gg, 256, SMEM_B>>>(nullptr, (uint32_t*)ZxH, (const __half*)inpH, KPAD,
                                (const __half*)wxH, KPAD, G4, KPAD, nullptr, partX);
    gemm_h<<<gg, 256, SMEM_B>>>(nullptr, (uint32_t*)ZhH, (const __half*)h00H, H_SZ,
                                (const __half*)wh0H, H_SZ, G4, H_SZ, nullptr, partH);
    stats_final<<<G4 / 256, 256>>>(gx0, bx0, gh0, bh0);
    cell_kernel<<<BH / 4 / 256, 256>>>((const uint2*)ZxH, (const uint2*)ZhH, c00,
                                       h1, (uint2*)h1H, c1);

    // layer 1
    gemm_h<<<gg, 256, SMEM_B>>>(nullptr, (uint32_t*)ZxH, (const __half*)h1H, H_SZ,
                                (const __half*)wx1H, H_SZ, G4, H_SZ, nullptr, partX);
    gemm_h<<<gg, 256, SMEM_B>>>(nullptr, (uint32_t*)ZhH, (const __half*)h01H, H_SZ,
                                (const __half*)wh1H, H_SZ, G4, H_SZ, nullptr, partH);
    stats_final<<<G4 / 256, 256>>>(gx1, bx1, gh1, bh1);
    cell_kernel<<<BH / 4 / 256, 256>>>((const uint2*)ZxH, (const uint2*)ZhH, c01,
                                       h2, (uint2*)h2H, c2);

    // output projection: fp32 + bias
    gemm_h<<<go, 256, SMEM_B>>>(out, nullptr, (const __half*)h2H, H_SZ,
                                (const __half*)woH, H_SZ, OUTF, H_SZ, bo, nullptr);
}